// round 12
// baseline (speedup 1.0000x reference)
#include <cuda_runtime.h>
#include <cuda_fp16.h>
#include <math.h>
#include <stdint.h>

#define BZ   128
#define T    32
#define D    768
#define DFF  3072
#define NE   8
#define NROWS 256
#define OUT_ELEMS (NROWS*T*D)
#define MAX_TILES 72

#define NT        256                 // CTA N tile
#define KC        128                 // K chunk
#define STAGES    2
#define AS_H      136                 // A smem row stride (halves), LDSM-clean
#define BS_H      264                 // B smem k-row stride (halves), LDSM-clean
#define A_STAGE_H (128*AS_H)          // 17408 halves
#define B_STAGE_H (KC*BS_H)           // 33792 halves
#define STAGE_H   (A_STAGE_H + B_STAGE_H)      // 51200 halves
#define SMEM_BYTES (STAGES*STAGE_H*2)          // 204800 B

// ---------------- scratch ---------------------------------------------------
__device__ int   g_sel[NROWS];
__device__ int   g_perm[NROWS];
__device__ int   g_tile_e[MAX_TILES];
__device__ int   g_tile_p0[MAX_TILES];
__device__ int   g_tile_rows[MAX_TILES];
__device__ int   g_ntiles;
__device__ __half g_xh[(size_t)BZ*T*D];        // fp16 copy of x
__device__ __half g_h[(size_t)NROWS*T*DFF];    // fp16 intermediate, grouped
__device__ __half g_w1h[(size_t)NE*D*DFF];     // fp16 W1
__device__ __half g_w2h[(size_t)NE*DFF*D];     // fp16 W2

__device__ __forceinline__ float gelu_exact(float v) {
    return 0.5f * v * (1.0f + erff(v * 0.70710678118654752f));
}
__device__ __forceinline__ uint32_t pack_h2(float lo, float hi) {
    uint32_t d;
    asm("cvt.rn.f16x2.f32 %0, %1, %2;" : "=r"(d) : "f"(hi), "f"(lo));
    return d;
}
__device__ __forceinline__ void mma_f16(float* c,
                                        uint32_t a0, uint32_t a1, uint32_t a2, uint32_t a3,
                                        uint32_t b0, uint32_t b1) {
    asm volatile(
        "mma.sync.aligned.m16n8k16.row.col.f32.f16.f16.f32 "
        "{%0,%1,%2,%3}, {%4,%5,%6,%7}, {%8,%9}, {%0,%1,%2,%3};"
        : "+f"(c[0]), "+f"(c[1]), "+f"(c[2]), "+f"(c[3])
        : "r"(a0), "r"(a1), "r"(a2), "r"(a3), "r"(b0), "r"(b1));
}
__device__ __forceinline__ void ldsm4(uint32_t* r, uint32_t addr) {
    asm volatile("ldmatrix.sync.aligned.m8n8.x4.shared.b16 {%0,%1,%2,%3}, [%4];"
        : "=r"(r[0]), "=r"(r[1]), "=r"(r[2]), "=r"(r[3]) : "r"(addr));
}
__device__ __forceinline__ void ldsm4t(uint32_t* r, uint32_t addr) {
    asm volatile("ldmatrix.sync.aligned.m8n8.x4.trans.shared.b16 {%0,%1,%2,%3}, [%4];"
        : "=r"(r[0]), "=r"(r[1]), "=r"(r[2]), "=r"(r[3]) : "r"(addr));
}
__device__ __forceinline__ void cp16(uint32_t saddr, const void* g) {
    asm volatile("cp.async.cg.shared.global [%0], [%1], 16;" :: "r"(saddr), "l"(g));
}

// ---------------- kernel 0a: x -> fp16 --------------------------------------
__global__ void half_x_kernel(const float* __restrict__ x) {
    int i = blockIdx.x * blockDim.x + threadIdx.x;
    const int n4 = BZ*T*D/4;
    if (i < n4) {
        float4 v = ((const float4*)x)[i];
        ((uint2*)g_xh)[i] = make_uint2(pack_h2(v.x, v.y), pack_h2(v.z, v.w));
    }
}

// ---------------- kernel 0b: W1,W2 -> fp16 ----------------------------------
__global__ void wcvt_kernel(const float* __restrict__ W1,
                            const float* __restrict__ W2) {
    size_t i = (size_t)blockIdx.x * blockDim.x + threadIdx.x;
    const size_t n4 = (size_t)NE*D*DFF/4;
    if (i < n4) {
        float4 a = ((const float4*)W1)[i];
        ((uint2*)g_w1h)[i] = make_uint2(pack_h2(a.x, a.y), pack_h2(a.z, a.w));
        float4 b = ((const float4*)W2)[i];
        ((uint2*)g_w2h)[i] = make_uint2(pack_h2(b.x, b.y), pack_h2(b.z, b.w));
    }
}

// ---------------- kernel 1: fused avg + router ------------------------------
__global__ void avg_router_kernel(const float* __restrict__ x,
                                  const float* __restrict__ Wg,
                                  float* __restrict__ dout, int out_size) {
    __shared__ float xa[D];
    int b = blockIdx.x;
    for (int d = threadIdx.x; d < D; d += blockDim.x) {
        float s = 0.f;
        #pragma unroll
        for (int t = 0; t < T; t++) s += x[((size_t)b*T + t)*D + d];
        xa[d] = s * (1.0f / T);
    }
    __syncthreads();
    if (threadIdx.x < 32) {
        int lane = threadIdx.x;
        int e = lane & 7;
        int chunk = lane >> 3;
        float part = 0.f;
        for (int d = chunk*192; d < (chunk+1)*192; d++) part += xa[d] * Wg[d*NE + e];
        part += __shfl_down_sync(0xffffffffu, part, 16);
        part += __shfl_down_sync(0xffffffffu, part, 8);
        float lv[NE];
        #pragma unroll
        for (int i = 0; i < NE; i++) lv[i] = __shfl_sync(0xffffffffu, part, i);
        if (lane == 0) {
            float mx = lv[0];
            #pragma unroll
            for (int i = 1; i < NE; i++) mx = fmaxf(mx, lv[i]);
            float p[NE]; float sum = 0.f;
            #pragma unroll
            for (int i = 0; i < NE; i++) { p[i] = __expf(lv[i] - mx); sum += p[i]; }
            float inv = 1.0f / sum;
            #pragma unroll
            for (int i = 0; i < NE; i++) p[i] *= inv;
            int i0 = 0;
            #pragma unroll
            for (int i = 1; i < NE; i++) if (p[i] > p[i0]) i0 = i;
            int i1 = (i0 == 0) ? 1 : 0;
            #pragma unroll
            for (int i = 0; i < NE; i++) if (i != i0 && p[i] > p[i1]) i1 = i;
            g_sel[2*b] = i0; g_sel[2*b+1] = i1;
            if (out_size >= OUT_ELEMS + 2*NROWS) {
                dout[OUT_ELEMS + 2*b]             = p[i0];
                dout[OUT_ELEMS + 2*b + 1]         = p[i1];
                dout[OUT_ELEMS + NROWS + 2*b]     = (float)i0;
                dout[OUT_ELEMS + NROWS + 2*b + 1] = (float)i1;
            }
        }
    }
}

// ---------------- kernel 2: group rows by expert ----------------------------
__global__ void group_kernel() {
    __shared__ int ssel[NROWS];
    __shared__ int shist[NE];
    __shared__ int soff[NE];
    int t = threadIdx.x;
    if (t < NE) shist[t] = 0;
    __syncthreads();
    ssel[t] = g_sel[t];
    __syncthreads();
    atomicAdd(&shist[ssel[t]], 1);
    __syncthreads();
    if (t == 0) {
        int pos = 0, tiles = 0;
        for (int e = 0; e < NE; e++) {
            soff[e] = pos;
            int cnt = shist[e];
            for (int r = 0; r < cnt; r += 4) {
                g_tile_e[tiles] = e; g_tile_p0[tiles] = pos + r;
                g_tile_rows[tiles] = min(4, cnt - r); tiles++;
            }
            pos += cnt;
        }
        g_ntiles = tiles;
    }
    __syncthreads();
    int mysel = ssel[t], rank = 0;
    for (int m = 0; m < NROWS; m++)
        if (m < t && ssel[m] == mysel) rank++;
    g_perm[soff[mysel] + rank] = t;
}

// ---------------- fp16 m16n8k16 GEMM, KC=128, 2-stage cp.async --------------
// PHASE 1: g_h = fp16(gelu(Xh_perm @ W1h[e] + b1[e]));  K=768,  N=3072
// PHASE 2 (split-K=2): out[perm] += g_h @ W2h[e](+b2 on kp0); K=1536/part
// CTA 128x256, 512 threads / 16 warps (2m x 8n), warp tile 64x32.
template<int PHASE>
__global__ __launch_bounds__(512, 1) void ffn_mma(
    const float* __restrict__ b1f, const float* __restrict__ b2f,
    float* __restrict__ out)
{
    const int mt = blockIdx.x;
    if (mt >= g_ntiles) return;
    const int e     = g_tile_e[mt];
    const int p0    = g_tile_p0[mt];
    const int nrows = g_tile_rows[mt];
    const int kp    = (PHASE == 2) ? blockIdx.z : 0;
    const int NF    = (PHASE == 1) ? DFF : D;
    const int kbase = (PHASE == 2) ? kp * (DFF/2) : 0;
    const int NC    = ((PHASE == 1) ? D : DFF/2) / KC;
    const __half* __restrict__ Bsrc = (PHASE == 1) ? (g_w1h + (size_t)e*D*DFF)
                                                   : (g_w2h + (size_t)e*DFF*D);
    const int n0 = blockIdx.y * NT;
    const int tid = threadIdx.x, wid = tid >> 5, lane = tid & 31;

    extern __shared__ __half smh[];
    uint32_t sbase = (uint32_t)__cvta_generic_to_shared(smh);

    // ---- A loader: 128 rows x 128 halves (16x16B segs), 4 thr/row x 4 segs
    const int arow = tid >> 2, aseg = (tid & 3) * 4;
    const __half* aglob;
    {
        int r = ((arow >> 5) < nrows) ? arow : (arow & 31);
        if (PHASE == 1) {
            int n = g_perm[p0 + (r >> 5)];
            aglob = g_xh + ((size_t)(n >> 1)*T + (r & 31)) * (size_t)D;
        } else {
            aglob = g_h + ((size_t)(p0*T + r)) * (size_t)DFF;
        }
    }
    // ---- B loader: 128 k-rows x 256 halves (32x16B segs), 4 thr/row x 8 segs
    const int brow = tid >> 2, bseg = tid & 3;
    const __half* bglob = Bsrc + (size_t)brow*NF + n0;

    uint32_t aSts[STAGES], bSts[STAGES];
    #pragma unroll
    for (int s = 0; s < STAGES; s++) {
        aSts[s] = sbase + (s*STAGE_H + arow*AS_H)*2;
        bSts[s] = sbase + (s*STAGE_H + A_STAGE_H + brow*BS_H)*2;
    }

    #define ISSUE(k0, s) do {                                                 \
        _Pragma("unroll")                                                     \
        for (int i = 0; i < 4; i++)                                           \
            cp16(aSts[s] + (aseg + i)*16, aglob + (k0) + (aseg + i)*8);       \
        _Pragma("unroll")                                                     \
        for (int i = 0; i < 8; i++)                                           \
            cp16(bSts[s] + (bseg + 4*i)*16,                                   \
                 bglob + (size_t)(k0)*NF + (bseg + 4*i)*8);                   \
    } while (0)

    // ---- ldmatrix lane bases ----
    const int wm = (wid & 1) * 64;
    const int wn = (wid >> 1) * 32;
    const int lm = lane >> 3;
    const int lr = lane & 7;
    uint32_t aLd[STAGES], bLd[STAGES];
    #pragma unroll
    for (int s = 0; s < STAGES; s++) {
        aLd[s] = sbase + (s*STAGE_H + (wm + (lm & 1)*8 + lr)*AS_H + (lm >> 1)*8)*2;
        bLd[s] = sbase + (s*STAGE_H + A_STAGE_H
                          + ((lm & 1)*8 + lr)*BS_H + wn + (lm >> 1)*8)*2;
    }

    float acc[4][4][4];
    #pragma unroll
    for (int i = 0; i < 4; i++)
        #pragma unroll
        for (int j = 0; j < 4; j++)
            #pragma unroll
            for (int q = 0; q < 4; q++) acc[i][j][q] = 0.f;

    // 8 k16-slices per chunk
    #define CONSUME(aL, bL) do {                                              \
        _Pragma("unroll")                                                     \
        for (int ks = 0; ks < 8; ks++) {                                      \
            uint32_t af[4][4], bf[2][4];                                      \
            _Pragma("unroll")                                                 \
            for (int mi = 0; mi < 4; mi++)                                    \
                ldsm4(af[mi], (aL) + (mi*16*AS_H + ks*16)*2);                 \
            _Pragma("unroll")                                                 \
            for (int nj = 0; nj < 2; nj++)                                    \
                ldsm4t(bf[nj], (bL) + (ks*16*BS_H + nj*16)*2);                \
            _Pragma("unroll")                                                 \
            for (int mi = 0; mi < 4; mi++) {                                  \
                _Pragma("unroll")                                             \
                for (int nj = 0; nj < 2; nj++) {                              \
                    mma_f16(acc[mi][2*nj],   af[mi][0], af[mi][1], af[mi][2], \
                            af[mi][3], bf[nj][0], bf[nj][1]);                 \
                    mma_f16(acc[mi][2*nj+1], af[mi][0], af[mi][1], af[mi][2], \
                            af[mi][3], bf[nj][2], bf[nj][3]);                 \
                }                                                             \
            }                                                                 \
        }                                                                     \
    } while (0)

    // ---- prologue: chunk 0 in flight ----
    ISSUE(kbase, 0);
    asm volatile("cp.async.commit_group;" ::: "memory");

    // ---- main loop: one barrier per KC=128 chunk ----
    for (int c = 0; c < NC; c++) {
        asm volatile("cp.async.wait_group 0;" ::: "memory");   // chunk c landed
        __syncthreads();            // visible to all; consume(c-1) done by all
        if (c + 1 < NC) {
            ISSUE(kbase + (c + 1)*KC, (c + 1) & 1);
            asm volatile("cp.async.commit_group;" ::: "memory");
        }
        if (c & 1) CONSUME(aLd[1], bLd[1]);
        else       CONSUME(aLd[0], bLd[0]);
    }

    // ---- epilogue ----
    const int g = lane >> 2, t4 = lane & 3;
    const float* bias = (PHASE == 1) ? (b1f + e*DFF + n0) : (b2f + e*D + n0);
    #pragma unroll
    for (int mi = 0; mi < 4; mi++) {
        #pragma unroll
        for (int h = 0; h < 2; h++) {
            int r = wm + 16*mi + g + 8*h;
            int br = r >> 5;
            if (br >= nrows) continue;
            if (PHASE == 1) {
                __half* dst = g_h + ((size_t)(p0*T + r)) * (size_t)DFF + n0;
                #pragma unroll
                for (int ni = 0; ni < 4; ni++) {
                    int col = wn + 8*ni + 2*t4;
                    float v0 = gelu_exact(acc[mi][ni][2*h + 0] + bias[col]);
                    float v1 = gelu_exact(acc[mi][ni][2*h + 1] + bias[col + 1]);
                    *(uint32_t*)(dst + col) = pack_h2(v0, v1);
                }
            } else {
                int n = g_perm[p0 + br];
                float* dst = out + ((size_t)n*T + (r & 31)) * (size_t)D + n0;
                #pragma unroll
                for (int ni = 0; ni < 4; ni++) {
                    int col = wn + 8*ni + 2*t4;
                    float v0 = acc[mi][ni][2*h + 0];
                    float v1 = acc[mi][ni][2*h + 1];
                    if (kp == 0) { v0 += bias[col]; v1 += bias[col + 1]; }
                    atomicAdd(dst + col,     v0);   // 2 contributions onto 0:
                    atomicAdd(dst + col + 1, v1);   // order-invariant
                }
            }
        }
    }
    #undef ISSUE
    #undef CONSUME
}

// ---------------- launch ----------------------------------------------------
extern "C" void kernel_launch(void* const* d_in, const int* in_sizes, int n_in,
                              void* d_out, int out_size) {
    const float* x  = (const float*)d_in[0];
    const float* Wg = (const float*)d_in[2];
    const float* W1 = (const float*)d_in[3];
    const float* b1 = (const float*)d_in[4];
    const float* W2 = (const float*)d_in[5];
    const float* b2 = (const float*)d_in[6];
    float* out = (float*)d_out;

    cudaFuncSetAttribute(ffn_mma<1>, cudaFuncAttributeMaxDynamicSharedMemorySize, SMEM_BYTES);
    cudaFuncSetAttribute(ffn_mma<2>, cudaFuncAttributeMaxDynamicSharedMemorySize, SMEM_BYTES);

    cudaMemsetAsync(out, 0, (size_t)OUT_ELEMS * sizeof(float));
    wcvt_kernel<<<(int)(((size_t)NE*D*DFF/4 + 255)/256), 256>>>(W1, W2);
    half_x_kernel<<<(BZ*T*D/4 + 255)/256, 256>>>(x);
    avg_router_kernel<<<BZ, 256>>>(x, Wg, out, out_size);
    group_kernel<<<1, NROWS>>>();
    ffn_mma<1><<<dim3(MAX_TILES, DFF/NT),  512, SMEM_BYTES>>>(b1, b2, out);
    ffn_mma<2><<<dim3(MAX_TILES, D/NT, 2), 512, SMEM_BYTES>>>(b1, b2, out);
}

// round 13
// speedup vs baseline: 1.0788x; 1.0788x over previous
#include <cuda_runtime.h>
#include <cuda_fp16.h>
#include <math.h>
#include <stdint.h>

#define BZ   128
#define T    32
#define D    768
#define DFF  3072
#define NE   8
#define NROWS 256
#define OUT_ELEMS (NROWS*T*D)
#define MAX_TILES 72

#define NT        256                 // CTA N tile
#define KC        64                  // K chunk
#define STAGES    3
#define AS_H      72                  // A smem row stride (halves), LDSM-clean
#define BS_H      264                 // B smem k-row stride (halves), LDSM-clean
#define A_STAGE_H (128*AS_H)          // 9216 halves
#define B_STAGE_H (KC*BS_H)           // 16896 halves
#define STAGE_H   (A_STAGE_H + B_STAGE_H)      // 26112 halves
#define SMEM_BYTES (STAGES*STAGE_H*2)          // 156672 B

// ---------------- scratch ---------------------------------------------------
__device__ int   g_sel[NROWS];
__device__ int   g_perm[NROWS];
__device__ int   g_tile_e[MAX_TILES];
__device__ int   g_tile_p0[MAX_TILES];
__device__ int   g_tile_rows[MAX_TILES];
__device__ int   g_ntiles;
__device__ __half g_xh[(size_t)BZ*T*D];        // fp16 copy of x
__device__ __half g_h[(size_t)NROWS*T*DFF];    // fp16 intermediate, grouped
__device__ __half g_w1h[(size_t)NE*D*DFF];     // fp16 W1
__device__ __half g_w2h[(size_t)NE*DFF*D];     // fp16 W2

__device__ __forceinline__ float gelu_exact(float v) {
    return 0.5f * v * (1.0f + erff(v * 0.70710678118654752f));
}
__device__ __forceinline__ uint32_t pack_h2(float lo, float hi) {
    uint32_t d;
    asm("cvt.rn.f16x2.f32 %0, %1, %2;" : "=r"(d) : "f"(hi), "f"(lo));
    return d;
}
__device__ __forceinline__ void mma_f16(float* c,
                                        uint32_t a0, uint32_t a1, uint32_t a2, uint32_t a3,
                                        uint32_t b0, uint32_t b1) {
    asm volatile(
        "mma.sync.aligned.m16n8k16.row.col.f32.f16.f16.f32 "
        "{%0,%1,%2,%3}, {%4,%5,%6,%7}, {%8,%9}, {%0,%1,%2,%3};"
        : "+f"(c[0]), "+f"(c[1]), "+f"(c[2]), "+f"(c[3])
        : "r"(a0), "r"(a1), "r"(a2), "r"(a3), "r"(b0), "r"(b1));
}
__device__ __forceinline__ void ldsm4(uint32_t* r, uint32_t addr) {
    asm volatile("ldmatrix.sync.aligned.m8n8.x4.shared.b16 {%0,%1,%2,%3}, [%4];"
        : "=r"(r[0]), "=r"(r[1]), "=r"(r[2]), "=r"(r[3]) : "r"(addr));
}
__device__ __forceinline__ void ldsm4t(uint32_t* r, uint32_t addr) {
    asm volatile("ldmatrix.sync.aligned.m8n8.x4.trans.shared.b16 {%0,%1,%2,%3}, [%4];"
        : "=r"(r[0]), "=r"(r[1]), "=r"(r[2]), "=r"(r[3]) : "r"(addr));
}
__device__ __forceinline__ void cp16(uint32_t saddr, const void* g) {
    asm volatile("cp.async.cg.shared.global [%0], [%1], 16;" :: "r"(saddr), "l"(g));
}

// ---------------- kernel 0a: x -> fp16 --------------------------------------
__global__ void half_x_kernel(const float* __restrict__ x) {
    int i = blockIdx.x * blockDim.x + threadIdx.x;
    const int n4 = BZ*T*D/4;
    if (i < n4) {
        float4 v = ((const float4*)x)[i];
        ((uint2*)g_xh)[i] = make_uint2(pack_h2(v.x, v.y), pack_h2(v.z, v.w));
    }
}

// ---------------- kernel 0b/0c: W1 / W2 -> fp16 ------------------------------
__global__ void wcvt1_kernel(const float* __restrict__ W1) {
    size_t i = (size_t)blockIdx.x * blockDim.x + threadIdx.x;
    const size_t n4 = (size_t)NE*D*DFF/4;
    if (i < n4) {
        float4 a = ((const float4*)W1)[i];
        ((uint2*)g_w1h)[i] = make_uint2(pack_h2(a.x, a.y), pack_h2(a.z, a.w));
    }
}
__global__ void wcvt2_kernel(const float* __restrict__ W2) {
    size_t i = (size_t)blockIdx.x * blockDim.x + threadIdx.x;
    const size_t n4 = (size_t)NE*DFF*D/4;
    if (i < n4) {
        float4 b = ((const float4*)W2)[i];
        ((uint2*)g_w2h)[i] = make_uint2(pack_h2(b.x, b.y), pack_h2(b.z, b.w));
    }
}

// ---------------- kernel 1: fused avg + router ------------------------------
__global__ void avg_router_kernel(const float* __restrict__ x,
                                  const float* __restrict__ Wg,
                                  float* __restrict__ dout, int out_size) {
    __shared__ float xa[D];
    int b = blockIdx.x;
    for (int d = threadIdx.x; d < D; d += blockDim.x) {
        float s = 0.f;
        #pragma unroll
        for (int t = 0; t < T; t++) s += x[((size_t)b*T + t)*D + d];
        xa[d] = s * (1.0f / T);
    }
    __syncthreads();
    if (threadIdx.x < 32) {
        int lane = threadIdx.x;
        int e = lane & 7;
        int chunk = lane >> 3;
        float part = 0.f;
        for (int d = chunk*192; d < (chunk+1)*192; d++) part += xa[d] * Wg[d*NE + e];
        part += __shfl_down_sync(0xffffffffu, part, 16);
        part += __shfl_down_sync(0xffffffffu, part, 8);
        float lv[NE];
        #pragma unroll
        for (int i = 0; i < NE; i++) lv[i] = __shfl_sync(0xffffffffu, part, i);
        if (lane == 0) {
            float mx = lv[0];
            #pragma unroll
            for (int i = 1; i < NE; i++) mx = fmaxf(mx, lv[i]);
            float p[NE]; float sum = 0.f;
            #pragma unroll
            for (int i = 0; i < NE; i++) { p[i] = __expf(lv[i] - mx); sum += p[i]; }
            float inv = 1.0f / sum;
            #pragma unroll
            for (int i = 0; i < NE; i++) p[i] *= inv;
            int i0 = 0;
            #pragma unroll
            for (int i = 1; i < NE; i++) if (p[i] > p[i0]) i0 = i;
            int i1 = (i0 == 0) ? 1 : 0;
            #pragma unroll
            for (int i = 0; i < NE; i++) if (i != i0 && p[i] > p[i1]) i1 = i;
            g_sel[2*b] = i0; g_sel[2*b+1] = i1;
            if (out_size >= OUT_ELEMS + 2*NROWS) {
                dout[OUT_ELEMS + 2*b]             = p[i0];
                dout[OUT_ELEMS + 2*b + 1]         = p[i1];
                dout[OUT_ELEMS + NROWS + 2*b]     = (float)i0;
                dout[OUT_ELEMS + NROWS + 2*b + 1] = (float)i1;
            }
        }
    }
}

// ---------------- kernel 2: group rows by expert ----------------------------
__global__ void group_kernel() {
    __shared__ int ssel[NROWS];
    __shared__ int shist[NE];
    __shared__ int soff[NE];
    int t = threadIdx.x;
    if (t < NE) shist[t] = 0;
    __syncthreads();
    ssel[t] = g_sel[t];
    __syncthreads();
    atomicAdd(&shist[ssel[t]], 1);
    __syncthreads();
    if (t == 0) {
        int pos = 0, tiles = 0;
        for (int e = 0; e < NE; e++) {
            soff[e] = pos;
            int cnt = shist[e];
            for (int r = 0; r < cnt; r += 4) {
                g_tile_e[tiles] = e; g_tile_p0[tiles] = pos + r;
                g_tile_rows[tiles] = min(4, cnt - r); tiles++;
            }
            pos += cnt;
        }
        g_ntiles = tiles;
    }
    __syncthreads();
    int mysel = ssel[t], rank = 0;
    for (int m = 0; m < NROWS; m++)
        if (m < t && ssel[m] == mysel) rank++;
    g_perm[soff[mysel] + rank] = t;
}

// ---------------- fp16 m16n8k16 GEMM, all-cp.async 3-stage ------------------
// PHASE 1: g_h = fp16(gelu(Xh_perm @ W1h[e] + b1[e]));  K=768,  N=3072
// PHASE 2 (split-K=2): out[perm] += g_h @ W2h[e](+b2 on kp0); K=1536/part
// CTA 128x256, 512 threads / 16 warps (2m x 8n), warp tile 64x32.
template<int PHASE>
__global__ __launch_bounds__(512, 1) void ffn_mma(
    const float* __restrict__ b1f, const float* __restrict__ b2f,
    float* __restrict__ out)
{
    const int mt = blockIdx.x;
    if (mt >= g_ntiles) return;
    const int e     = g_tile_e[mt];
    const int p0    = g_tile_p0[mt];
    const int nrows = g_tile_rows[mt];
    const int kp    = (PHASE == 2) ? blockIdx.z : 0;
    const int NF    = (PHASE == 1) ? DFF : D;
    const int kbase = (PHASE == 2) ? kp * (DFF/2) : 0;
    const int NC    = ((PHASE == 1) ? D : DFF/2) / KC;
    const __half* __restrict__ Bsrc = (PHASE == 1) ? (g_w1h + (size_t)e*D*DFF)
                                                   : (g_w2h + (size_t)e*DFF*D);
    const int n0 = blockIdx.y * NT;
    const int tid = threadIdx.x, wid = tid >> 5, lane = tid & 31;

    extern __shared__ __half smh[];
    uint32_t sbase = (uint32_t)__cvta_generic_to_shared(smh);

    // ---- A loader: 128 rows x 64 halves (8x16B segs), 4 thr/row x 2 segs ----
    const int arow = tid >> 2, aseg = (tid & 3) * 2;
    const __half* aglob;
    {
        int r = ((arow >> 5) < nrows) ? arow : (arow & 31);
        if (PHASE == 1) {
            int n = g_perm[p0 + (r >> 5)];
            aglob = g_xh + ((size_t)(n >> 1)*T + (r & 31)) * (size_t)D;
        } else {
            aglob = g_h + ((size_t)(p0*T + r)) * (size_t)DFF;
        }
    }
    // ---- B loader: 64 k-rows x 256 halves (32x16B segs), 8 thr/row x 4 segs
    const int brow = tid >> 3, bseg = tid & 7;
    const __half* bglob = Bsrc + (size_t)brow*NF + n0;

    uint32_t aSts[STAGES], bSts[STAGES];
    #pragma unroll
    for (int s = 0; s < STAGES; s++) {
        aSts[s] = sbase + (s*STAGE_H + arow*AS_H)*2;
        bSts[s] = sbase + (s*STAGE_H + A_STAGE_H + brow*BS_H)*2;
    }

    #define ISSUE(k0, s) do {                                                 \
        cp16(aSts[s] + (aseg+0)*16, aglob + (k0) + (aseg+0)*8);               \
        cp16(aSts[s] + (aseg+1)*16, aglob + (k0) + (aseg+1)*8);               \
        _Pragma("unroll")                                                     \
        for (int i = 0; i < 4; i++)                                           \
            cp16(bSts[s] + (bseg + 8*i)*16,                                   \
                 bglob + (size_t)(k0)*NF + (bseg + 8*i)*8);                   \
    } while (0)

    // ---- ldmatrix lane bases ----
    const int wm = (wid & 1) * 64;
    const int wn = (wid >> 1) * 32;
    const int lm = lane >> 3;
    const int lr = lane & 7;
    uint32_t aLd[STAGES], bLd[STAGES];
    #pragma unroll
    for (int s = 0; s < STAGES; s++) {
        aLd[s] = sbase + (s*STAGE_H + (wm + (lm & 1)*8 + lr)*AS_H + (lm >> 1)*8)*2;
        bLd[s] = sbase + (s*STAGE_H + A_STAGE_H
                          + ((lm & 1)*8 + lr)*BS_H + wn + (lm >> 1)*8)*2;
    }

    float acc[4][4][4];
    #pragma unroll
    for (int i = 0; i < 4; i++)
        #pragma unroll
        for (int j = 0; j < 4; j++)
            #pragma unroll
            for (int q = 0; q < 4; q++) acc[i][j][q] = 0.f;

    #define CONSUME(aL, bL) do {                                              \
        _Pragma("unroll")                                                     \
        for (int ks = 0; ks < 4; ks++) {                                      \
            uint32_t af[4][4], bf[2][4];                                      \
            _Pragma("unroll")                                                 \
            for (int mi = 0; mi < 4; mi++)                                    \
                ldsm4(af[mi], (aL) + (mi*16*AS_H + ks*16)*2);                 \
            _Pragma("unroll")                                                 \
            for (int nj = 0; nj < 2; nj++)                                    \
                ldsm4t(bf[nj], (bL) + (ks*16*BS_H + nj*16)*2);                \
            _Pragma("unroll")                                                 \
            for (int mi = 0; mi < 4; mi++) {                                  \
                _Pragma("unroll")                                             \
                for (int nj = 0; nj < 2; nj++) {                              \
                    mma_f16(acc[mi][2*nj],   af[mi][0], af[mi][1], af[mi][2], \
                            af[mi][3], bf[nj][0], bf[nj][1]);                 \
                    mma_f16(acc[mi][2*nj+1], af[mi][0], af[mi][1], af[mi][2], \
                            af[mi][3], bf[nj][2], bf[nj][3]);                 \
                }                                                             \
            }                                                                 \
        }                                                                     \
    } while (0)

    // ---- prologue: chunks 0,1 in flight ----
    ISSUE(kbase, 0);
    asm volatile("cp.async.commit_group;" ::: "memory");
    ISSUE(kbase + KC, 1);
    asm volatile("cp.async.commit_group;" ::: "memory");

    // ---- main loop: one barrier per chunk, loads fully overlapped ----
    for (int c = 0; c < NC; c++) {
        asm volatile("cp.async.wait_group 1;" ::: "memory");   // chunk c landed
        __syncthreads();           // visible to all; consume(c-1) done by all
        if (c + 2 < NC) ISSUE(kbase + (c + 2)*KC, (c + 2) % STAGES);
        asm volatile("cp.async.commit_group;" ::: "memory");
        switch (c % STAGES) {
            case 0: CONSUME(aLd[0], bLd[0]); break;
            case 1: CONSUME(aLd[1], bLd[1]); break;
            default: CONSUME(aLd[2], bLd[2]); break;
        }
    }

    // ---- epilogue ----
    const int g = lane >> 2, t4 = lane & 3;
    const float* bias = (PHASE == 1) ? (b1f + e*DFF + n0) : (b2f + e*D + n0);
    #pragma unroll
    for (int mi = 0; mi < 4; mi++) {
        #pragma unroll
        for (int h = 0; h < 2; h++) {
            int r = wm + 16*mi + g + 8*h;
            int br = r >> 5;
            if (br >= nrows) continue;
            if (PHASE == 1) {
                __half* dst = g_h + ((size_t)(p0*T + r)) * (size_t)DFF + n0;
                #pragma unroll
                for (int ni = 0; ni < 4; ni++) {
                    int col = wn + 8*ni + 2*t4;
                    float v0 = gelu_exact(acc[mi][ni][2*h + 0] + bias[col]);
                    float v1 = gelu_exact(acc[mi][ni][2*h + 1] + bias[col + 1]);
                    *(uint32_t*)(dst + col) = pack_h2(v0, v1);
                }
            } else {
                int n = g_perm[p0 + br];
                float* dst = out + ((size_t)n*T + (r & 31)) * (size_t)D + n0;
                #pragma unroll
                for (int ni = 0; ni < 4; ni++) {
                    int col = wn + 8*ni + 2*t4;
                    float v0 = acc[mi][ni][2*h + 0];
                    float v1 = acc[mi][ni][2*h + 1];
                    if (kp == 0) { v0 += bias[col]; v1 += bias[col + 1]; }
                    atomicAdd(dst + col,     v0);   // 2 contributions onto 0:
                    atomicAdd(dst + col + 1, v1);   // order-invariant
                }
            }
        }
    }
    #undef ISSUE
    #undef CONSUME
}

// ---------------- launch (multi-stream fork inside capture) ------------------
extern "C" void kernel_launch(void* const* d_in, const int* in_sizes, int n_in,
                              void* d_out, int out_size) {
    const float* x  = (const float*)d_in[0];
    const float* Wg = (const float*)d_in[2];
    const float* W1 = (const float*)d_in[3];
    const float* b1 = (const float*)d_in[4];
    const float* W2 = (const float*)d_in[5];
    const float* b2 = (const float*)d_in[6];
    float* out = (float*)d_out;

    // one-time resource creation (first call = correctness run, not captured)
    static cudaStream_t s2 = nullptr;
    static cudaEvent_t evStart = nullptr, evAux = nullptr, evB = nullptr;
    if (s2 == nullptr) {
        cudaStreamCreateWithFlags(&s2, cudaStreamNonBlocking);
        cudaEventCreateWithFlags(&evStart, cudaEventDisableTiming);
        cudaEventCreateWithFlags(&evAux,   cudaEventDisableTiming);
        cudaEventCreateWithFlags(&evB,     cudaEventDisableTiming);
        cudaFuncSetAttribute(ffn_mma<1>, cudaFuncAttributeMaxDynamicSharedMemorySize, SMEM_BYTES);
        cudaFuncSetAttribute(ffn_mma<2>, cudaFuncAttributeMaxDynamicSharedMemorySize, SMEM_BYTES);
    }

    const size_t w4 = (size_t)NE*D*DFF/4;

    // fork: side stream does router/group/half_x then W2 conversion
    cudaEventRecord(evStart, 0);
    cudaStreamWaitEvent(s2, evStart, 0);

    avg_router_kernel<<<BZ, 256, 0, s2>>>(x, Wg, out, out_size);
    group_kernel<<<1, NROWS, 0, s2>>>();
    half_x_kernel<<<(BZ*T*D/4 + 255)/256, 256, 0, s2>>>(x);
    cudaEventRecord(evAux, s2);
    wcvt2_kernel<<<(int)((w4 + 255)/256), 256, 0, s2>>>(W2);
    cudaEventRecord(evB, s2);

    // main stream: zero-init out, convert W1, then gemm1 (overlaps wcvt2)
    cudaMemsetAsync(out, 0, (size_t)OUT_ELEMS * sizeof(float), 0);
    wcvt1_kernel<<<(int)((w4 + 255)/256), 256>>>(W1);
    cudaStreamWaitEvent(0, evAux, 0);
    ffn_mma<1><<<dim3(MAX_TILES, DFF/NT),  512, SMEM_BYTES>>>(b1, b2, out);
    cudaStreamWaitEvent(0, evB, 0);
    ffn_mma<2><<<dim3(MAX_TILES, D/NT, 2), 512, SMEM_BYTES>>>(b1, b2, out);
}

// round 14
// speedup vs baseline: 1.1289x; 1.0465x over previous
#include <cuda_runtime.h>
#include <cuda_fp16.h>
#include <math.h>
#include <stdint.h>

#define BZ   128
#define T    32
#define D    768
#define DFF  3072
#define NE   8
#define NROWS 256
#define OUT_ELEMS (NROWS*T*D)
#define MAX_TILES 72

#define NT        256                 // CTA N tile
#define KC        64                  // K chunk
#define STAGES    4
#define AS_H      72                  // A smem row stride (halves), LDSM-clean
#define BS_H      264                 // B smem k-row stride (halves), LDSM-clean
#define A_STAGE_H (128*AS_H)          // 9216 halves
#define B_STAGE_H (KC*BS_H)           // 16896 halves
#define STAGE_H   (A_STAGE_H + B_STAGE_H)      // 26112 halves
#define SSZ       (STAGE_H*2)                  // stage bytes (52224)
#define SMEM_BYTES (STAGES*SSZ)                // 208896 B

// ---------------- scratch ---------------------------------------------------
__device__ int   g_sel[NROWS];
__device__ int   g_perm[NROWS];
__device__ int   g_tile_e[MAX_TILES];
__device__ int   g_tile_p0[MAX_TILES];
__device__ int   g_tile_rows[MAX_TILES];
__device__ int   g_ntiles;
__device__ __half g_xh[(size_t)BZ*T*D];        // fp16 copy of x
__device__ __half g_h[(size_t)NROWS*T*DFF];    // fp16 intermediate, grouped
__device__ __half g_w1h[(size_t)NE*D*DFF];     // fp16 W1
__device__ __half g_w2h[(size_t)NE*DFF*D];     // fp16 W2

__device__ __forceinline__ float gelu_exact(float v) {
    return 0.5f * v * (1.0f + erff(v * 0.70710678118654752f));
}
__device__ __forceinline__ uint32_t pack_h2(float lo, float hi) {
    uint32_t d;
    asm("cvt.rn.f16x2.f32 %0, %1, %2;" : "=r"(d) : "f"(hi), "f"(lo));
    return d;
}
__device__ __forceinline__ void mma_f16(float* c,
                                        uint32_t a0, uint32_t a1, uint32_t a2, uint32_t a3,
                                        uint32_t b0, uint32_t b1) {
    asm volatile(
        "mma.sync.aligned.m16n8k16.row.col.f32.f16.f16.f32 "
        "{%0,%1,%2,%3}, {%4,%5,%6,%7}, {%8,%9}, {%0,%1,%2,%3};"
        : "+f"(c[0]), "+f"(c[1]), "+f"(c[2]), "+f"(c[3])
        : "r"(a0), "r"(a1), "r"(a2), "r"(a3), "r"(b0), "r"(b1));
}
__device__ __forceinline__ void ldsm4(uint32_t* r, uint32_t addr) {
    asm volatile("ldmatrix.sync.aligned.m8n8.x4.shared.b16 {%0,%1,%2,%3}, [%4];"
        : "=r"(r[0]), "=r"(r[1]), "=r"(r[2]), "=r"(r[3]) : "r"(addr));
}
__device__ __forceinline__ void ldsm4t(uint32_t* r, uint32_t addr) {
    asm volatile("ldmatrix.sync.aligned.m8n8.x4.trans.shared.b16 {%0,%1,%2,%3}, [%4];"
        : "=r"(r[0]), "=r"(r[1]), "=r"(r[2]), "=r"(r[3]) : "r"(addr));
}
__device__ __forceinline__ void cp16(uint32_t saddr, const void* g) {
    asm volatile("cp.async.cg.shared.global [%0], [%1], 16;" :: "r"(saddr), "l"(g));
}

// ---------------- kernel 0a: x -> fp16 --------------------------------------
__global__ void half_x_kernel(const float* __restrict__ x) {
    int i = blockIdx.x * blockDim.x + threadIdx.x;
    const int n4 = BZ*T*D/4;
    if (i < n4) {
        float4 v = ((const float4*)x)[i];
        ((uint2*)g_xh)[i] = make_uint2(pack_h2(v.x, v.y), pack_h2(v.z, v.w));
    }
}

// ---------------- kernel 0b/0c: W1 / W2 -> fp16 ------------------------------
__global__ void wcvt1_kernel(const float* __restrict__ W1) {
    size_t i = (size_t)blockIdx.x * blockDim.x + threadIdx.x;
    const size_t n4 = (size_t)NE*D*DFF/4;
    if (i < n4) {
        float4 a = ((const float4*)W1)[i];
        ((uint2*)g_w1h)[i] = make_uint2(pack_h2(a.x, a.y), pack_h2(a.z, a.w));
    }
}
__global__ void wcvt2_kernel(const float* __restrict__ W2) {
    size_t i = (size_t)blockIdx.x * blockDim.x + threadIdx.x;
    const size_t n4 = (size_t)NE*DFF*D/4;
    if (i < n4) {
        float4 b = ((const float4*)W2)[i];
        ((uint2*)g_w2h)[i] = make_uint2(pack_h2(b.x, b.y), pack_h2(b.z, b.w));
    }
}

// ---------------- kernel 1: fused avg + router ------------------------------
__global__ void avg_router_kernel(const float* __restrict__ x,
                                  const float* __restrict__ Wg,
                                  float* __restrict__ dout, int out_size) {
    __shared__ float xa[D];
    int b = blockIdx.x;
    for (int d = threadIdx.x; d < D; d += blockDim.x) {
        float s = 0.f;
        #pragma unroll
        for (int t = 0; t < T; t++) s += x[((size_t)b*T + t)*D + d];
        xa[d] = s * (1.0f / T);
    }
    __syncthreads();
    if (threadIdx.x < 32) {
        int lane = threadIdx.x;
        int e = lane & 7;
        int chunk = lane >> 3;
        float part = 0.f;
        for (int d = chunk*192; d < (chunk+1)*192; d++) part += xa[d] * Wg[d*NE + e];
        part += __shfl_down_sync(0xffffffffu, part, 16);
        part += __shfl_down_sync(0xffffffffu, part, 8);
        float lv[NE];
        #pragma unroll
        for (int i = 0; i < NE; i++) lv[i] = __shfl_sync(0xffffffffu, part, i);
        if (lane == 0) {
            float mx = lv[0];
            #pragma unroll
            for (int i = 1; i < NE; i++) mx = fmaxf(mx, lv[i]);
            float p[NE]; float sum = 0.f;
            #pragma unroll
            for (int i = 0; i < NE; i++) { p[i] = __expf(lv[i] - mx); sum += p[i]; }
            float inv = 1.0f / sum;
            #pragma unroll
            for (int i = 0; i < NE; i++) p[i] *= inv;
            int i0 = 0;
            #pragma unroll
            for (int i = 1; i < NE; i++) if (p[i] > p[i0]) i0 = i;
            int i1 = (i0 == 0) ? 1 : 0;
            #pragma unroll
            for (int i = 0; i < NE; i++) if (i != i0 && p[i] > p[i1]) i1 = i;
            g_sel[2*b] = i0; g_sel[2*b+1] = i1;
            if (out_size >= OUT_ELEMS + 2*NROWS) {
                dout[OUT_ELEMS + 2*b]             = p[i0];
                dout[OUT_ELEMS + 2*b + 1]         = p[i1];
                dout[OUT_ELEMS + NROWS + 2*b]     = (float)i0;
                dout[OUT_ELEMS + NROWS + 2*b + 1] = (float)i1;
            }
        }
    }
}

// ---------------- kernel 2: group rows by expert ----------------------------
__global__ void group_kernel() {
    __shared__ int ssel[NROWS];
    __shared__ int shist[NE];
    __shared__ int soff[NE];
    int t = threadIdx.x;
    if (t < NE) shist[t] = 0;
    __syncthreads();
    ssel[t] = g_sel[t];
    __syncthreads();
    atomicAdd(&shist[ssel[t]], 1);
    __syncthreads();
    if (t == 0) {
        int pos = 0, tiles = 0;
        for (int e = 0; e < NE; e++) {
            soff[e] = pos;
            int cnt = shist[e];
            for (int r = 0; r < cnt; r += 4) {
                g_tile_e[tiles] = e; g_tile_p0[tiles] = pos + r;
                g_tile_rows[tiles] = min(4, cnt - r); tiles++;
            }
            pos += cnt;
        }
        g_ntiles = tiles;
    }
    __syncthreads();
    int mysel = ssel[t], rank = 0;
    for (int m = 0; m < NROWS; m++)
        if (m < t && ssel[m] == mysel) rank++;
    g_perm[soff[mysel] + rank] = t;
}

// ---------------- fp16 m16n8k16 GEMM, 4-stage, single consume body ----------
// PHASE 1: g_h = fp16(gelu(Xh_perm @ W1h[e] + b1[e]));  K=768,  N=3072
// PHASE 2 (split-K=2): out[perm] += g_h @ W2h[e](+b2 on kp0); K=1536/part
// CTA 128x256, 512 threads / 16 warps (2m x 8n), warp tile 64x32.
template<int PHASE>
__global__ __launch_bounds__(512, 1) void ffn_mma(
    const float* __restrict__ b1f, const float* __restrict__ b2f,
    float* __restrict__ out)
{
    const int mt = blockIdx.x;
    if (mt >= g_ntiles) return;
    const int e     = g_tile_e[mt];
    const int p0    = g_tile_p0[mt];
    const int nrows = g_tile_rows[mt];
    const int kp    = (PHASE == 2) ? blockIdx.z : 0;
    const int NF    = (PHASE == 1) ? DFF : D;
    const int kbase = (PHASE == 2) ? kp * (DFF/2) : 0;
    const int NC    = ((PHASE == 1) ? D : DFF/2) / KC;
    const __half* __restrict__ Bsrc = (PHASE == 1) ? (g_w1h + (size_t)e*D*DFF)
                                                   : (g_w2h + (size_t)e*DFF*D);
    const int n0 = blockIdx.y * NT;
    const int tid = threadIdx.x, wid = tid >> 5, lane = tid & 31;

    extern __shared__ __half smh[];
    uint32_t sbase = (uint32_t)__cvta_generic_to_shared(smh);

    // ---- A loader: 128 rows x 64 halves (8x16B segs), 4 thr/row x 2 segs ----
    const int arow = tid >> 2, aseg = (tid & 3) * 2;
    const __half* aglob;
    {
        int r = ((arow >> 5) < nrows) ? arow : (arow & 31);
        if (PHASE == 1) {
            int n = g_perm[p0 + (r >> 5)];
            aglob = g_xh + ((size_t)(n >> 1)*T + (r & 31)) * (size_t)D;
        } else {
            aglob = g_h + ((size_t)(p0*T + r)) * (size_t)DFF;
        }
    }
    // ---- B loader: 64 k-rows x 256 halves (32x16B segs), 8 thr/row x 4 segs
    const int brow = tid >> 3, bseg = tid & 7;
    const __half* bglob = Bsrc + (size_t)brow*NF + n0;

    // stage-0 bases; stage selected by running byte offset
    const uint32_t aStsB = sbase + (arow*AS_H)*2;
    const uint32_t bStsB = sbase + (A_STAGE_H + brow*BS_H)*2;

    #define ISSUE(k0, soff) do {                                              \
        cp16(aStsB + (soff) + (aseg+0)*16, aglob + (k0) + (aseg+0)*8);        \
        cp16(aStsB + (soff) + (aseg+1)*16, aglob + (k0) + (aseg+1)*8);        \
        _Pragma("unroll")                                                     \
        for (int i = 0; i < 4; i++)                                           \
            cp16(bStsB + (soff) + (bseg + 8*i)*16,                            \
                 bglob + (size_t)(k0)*NF + (bseg + 8*i)*8);                   \
    } while (0)

    // ---- ldmatrix lane bases (stage 0) ----
    const int wm = (wid & 1) * 64;
    const int wn = (wid >> 1) * 32;
    const int lm = lane >> 3;
    const int lr = lane & 7;
    const uint32_t aLdB = sbase + ((wm + (lm & 1)*8 + lr)*AS_H + (lm >> 1)*8)*2;
    const uint32_t bLdB = sbase + (A_STAGE_H + ((lm & 1)*8 + lr)*BS_H
                                   + wn + (lm >> 1)*8)*2;

    float acc[4][4][4];
    #pragma unroll
    for (int i = 0; i < 4; i++)
        #pragma unroll
        for (int j = 0; j < 4; j++)
            #pragma unroll
            for (int q = 0; q < 4; q++) acc[i][j][q] = 0.f;

    // ---- prologue: chunks 0..2 in flight ----
    ISSUE(kbase + 0*KC, 0*SSZ);
    asm volatile("cp.async.commit_group;" ::: "memory");
    ISSUE(kbase + 1*KC, 1*SSZ);
    asm volatile("cp.async.commit_group;" ::: "memory");
    ISSUE(kbase + 2*KC, 2*SSZ);
    asm volatile("cp.async.commit_group;" ::: "memory");

    uint32_t consOff = 0, issOff = 3*SSZ;

    // ---- main loop: single consume body, running stage offsets ----
    for (int c = 0; c < NC; c++) {
        asm volatile("cp.async.wait_group 2;" ::: "memory");  // chunk c landed
        __syncthreads();          // visible to all; consume(c-1) done by all
        if (c + 3 < NC) ISSUE(kbase + (c + 3)*KC, issOff);
        asm volatile("cp.async.commit_group;" ::: "memory");

        const uint32_t aL = aLdB + consOff;
        const uint32_t bL = bLdB + consOff;
        #pragma unroll
        for (int ks = 0; ks < 4; ks++) {
            uint32_t af[4][4], bf[2][4];
            #pragma unroll
            for (int mi = 0; mi < 4; mi++)
                ldsm4(af[mi], aL + (mi*16*AS_H + ks*16)*2);
            #pragma unroll
            for (int nj = 0; nj < 2; nj++)
                ldsm4t(bf[nj], bL + (ks*16*BS_H + nj*16)*2);
            #pragma unroll
            for (int mi = 0; mi < 4; mi++) {
                #pragma unroll
                for (int nj = 0; nj < 2; nj++) {
                    mma_f16(acc[mi][2*nj],   af[mi][0], af[mi][1], af[mi][2],
                            af[mi][3], bf[nj][0], bf[nj][1]);
                    mma_f16(acc[mi][2*nj+1], af[mi][0], af[mi][1], af[mi][2],
                            af[mi][3], bf[nj][2], bf[nj][3]);
                }
            }
        }
        consOff = (consOff == 3*SSZ) ? 0 : consOff + SSZ;
        issOff  = (issOff  == 3*SSZ) ? 0 : issOff  + SSZ;
    }

    // ---- epilogue ----
    const int g = lane >> 2, t4 = lane & 3;
    const float* bias = (PHASE == 1) ? (b1f + e*DFF + n0) : (b2f + e*D + n0);
    #pragma unroll
    for (int mi = 0; mi < 4; mi++) {
        #pragma unroll
        for (int h = 0; h < 2; h++) {
            int r = wm + 16*mi + g + 8*h;
            int br = r >> 5;
            if (br >= nrows) continue;
            if (PHASE == 1) {
                __half* dst = g_h + ((size_t)(p0*T + r)) * (size_t)DFF + n0;
                #pragma unroll
                for (int ni = 0; ni < 4; ni++) {
                    int col = wn + 8*ni + 2*t4;
                    float v0 = gelu_exact(acc[mi][ni][2*h + 0] + bias[col]);
                    float v1 = gelu_exact(acc[mi][ni][2*h + 1] + bias[col + 1]);
                    *(uint32_t*)(dst + col) = pack_h2(v0, v1);
                }
            } else {
                int n = g_perm[p0 + br];
                float* dst = out + ((size_t)n*T + (r & 31)) * (size_t)D + n0;
                #pragma unroll
                for (int ni = 0; ni < 4; ni++) {
                    int col = wn + 8*ni + 2*t4;
                    float v0 = acc[mi][ni][2*h + 0];
                    float v1 = acc[mi][ni][2*h + 1];
                    if (kp == 0) { v0 += bias[col]; v1 += bias[col + 1]; }
                    atomicAdd(dst + col,     v0);   // 2 contributions onto 0:
                    atomicAdd(dst + col + 1, v1);   // order-invariant
                }
            }
        }
    }
    #undef ISSUE
}

// ---------------- launch (multi-stream fork inside capture) ------------------
extern "C" void kernel_launch(void* const* d_in, const int* in_sizes, int n_in,
                              void* d_out, int out_size) {
    const float* x  = (const float*)d_in[0];
    const float* Wg = (const float*)d_in[2];
    const float* W1 = (const float*)d_in[3];
    const float* b1 = (const float*)d_in[4];
    const float* W2 = (const float*)d_in[5];
    const float* b2 = (const float*)d_in[6];
    float* out = (float*)d_out;

    static cudaStream_t s2 = nullptr;
    static cudaEvent_t evStart = nullptr, evAux = nullptr, evB = nullptr;
    if (s2 == nullptr) {
        cudaStreamCreateWithFlags(&s2, cudaStreamNonBlocking);
        cudaEventCreateWithFlags(&evStart, cudaEventDisableTiming);
        cudaEventCreateWithFlags(&evAux,   cudaEventDisableTiming);
        cudaEventCreateWithFlags(&evB,     cudaEventDisableTiming);
        cudaFuncSetAttribute(ffn_mma<1>, cudaFuncAttributeMaxDynamicSharedMemorySize, SMEM_BYTES);
        cudaFuncSetAttribute(ffn_mma<2>, cudaFuncAttributeMaxDynamicSharedMemorySize, SMEM_BYTES);
    }

    const size_t w4 = (size_t)NE*D*DFF/4;

    // fork: side stream does memset + router/group/half_x then W2 conversion
    cudaEventRecord(evStart, 0);
    cudaStreamWaitEvent(s2, evStart, 0);

    cudaMemsetAsync(out, 0, (size_t)OUT_ELEMS * sizeof(float), s2);
    avg_router_kernel<<<BZ, 256, 0, s2>>>(x, Wg, out, out_size);
    group_kernel<<<1, NROWS, 0, s2>>>();
    half_x_kernel<<<(BZ*T*D/4 + 255)/256, 256, 0, s2>>>(x);
    cudaEventRecord(evAux, s2);
    wcvt2_kernel<<<(int)((w4 + 255)/256), 256, 0, s2>>>(W2);
    cudaEventRecord(evB, s2);

    // main stream: convert W1, then gemm1 (overlaps wcvt2), then gemm2
    wcvt1_kernel<<<(int)((w4 + 255)/256), 256>>>(W1);
    cudaStreamWaitEvent(0, evAux, 0);
    ffn_mma<1><<<dim3(MAX_TILES, DFF/NT),  512, SMEM_BYTES>>>(b1, b2, out);
    cudaStreamWaitEvent(0, evB, 0);
    ffn_mma<2><<<dim3(MAX_TILES, D/NT, 2), 512, SMEM_BYTES>>>(b1, b2, out);
}